// round 10
// baseline (speedup 1.0000x reference)
#include <cuda_runtime.h>
#include <math.h>

#define BB 128
#define QQ 500
#define NCLS 80
#define TT 64
#define NT 1024
#define CSTR 513   // column-major stride: bank = (col + q) % 32 -> conflict-free everywhere
#define FULL 0xffffffffu
#define SMEM_SZ (TT * CSTR * 4)   // 131,328 B dynamic (Cm only)
#define DEADK 0xFFFFFFFFu

__device__ __forceinline__ unsigned f2ord(float f) {
    unsigned u = __float_as_uint(f);
    return (u & 0x80000000u) ? ~u : (u | 0x80000000u);
}

// warp-cooperative exact (value, ravel) top-2 over one smem column.
// Returns #1 in (v1,r1) and #2 in (v2,r2); v = f2ord(cost), r = ravel = q*64+col.
__device__ __forceinline__ void colscan2(const float* __restrict__ Cm, int col,
                                         int lane, unsigned& v1o, unsigned& r1o,
                                         unsigned& v2o, unsigned& r2o) {
    const float* p = Cm + col * CSTR;
    unsigned long long b1 = ~0ull, b2 = ~0ull;
    #pragma unroll
    for (int it = 0; it < 16; it++) {
        int q = lane + (it << 5);
        if (q < QQ) {
            unsigned long long k =
                ((unsigned long long)f2ord(p[q]) << 15) | (unsigned)((q << 6) | col);
            if (k < b1)      { b2 = b1; b1 = k; }
            else if (k < b2) { b2 = k; }
        }
    }
    unsigned lv = (unsigned)(b1 >> 15);
    unsigned m1 = __reduce_min_sync(FULL, lv);
    unsigned c1 = (lv == m1) ? (unsigned)(b1 & 0x7FFFull) : 0xFFFFFFFFu;
    unsigned r1 = __reduce_min_sync(FULL, c1);
    bool own = (lv == m1) && ((unsigned)(b1 & 0x7FFFull) == r1);

    unsigned long long c2k = own ? b2 : b1;
    unsigned lv2 = (unsigned)(c2k >> 15);
    unsigned m2 = __reduce_min_sync(FULL, lv2);
    unsigned c2 = (lv2 == m2) ? (unsigned)(c2k & 0x7FFFull) : 0xFFFFFFFFu;
    unsigned r2 = __reduce_min_sync(FULL, c2);

    v1o = m1; r1o = r1; v2o = m2; r2o = r2;
}

__global__ __launch_bounds__(NT, 1)
void hungarian_fused(const float* __restrict__ logits,   // [B,Q,C]
                     const float* __restrict__ pboxes,   // [B,Q,4]
                     const int*   __restrict__ tids,     // [B,T]
                     const float* __restrict__ tboxes,   // [B,T,4]
                     const float* __restrict__ imgsz,    // [B,4]
                     float*       __restrict__ out)
{
    extern __shared__ float Cm[];           // [64][513]
    __shared__ float4  s_tr[TT];
    __shared__ float4  s_tn[TT];
    __shared__ float   s_ta[TT];
    __shared__ int     s_cls[TT];
    __shared__ unsigned s_v1[TT], s_r1[TT], s_v2[TT], s_r2[TT];

    const int b = blockIdx.x, tid = threadIdx.x;
    const int lane = tid & 31, wrp = tid >> 5;

    const float inv0 = 1.0f / imgsz[b * 4 + 0];
    const float inv1 = 1.0f / imgsz[b * 4 + 1];
    const float inv2 = 1.0f / imgsz[b * 4 + 2];
    const float inv3 = 1.0f / imgsz[b * 4 + 3];

    if (tid < TT) {
        float4 tb = ((const float4*)tboxes)[b * TT + tid];
        s_tr[tid] = tb;
        s_tn[tid] = make_float4(tb.x * inv0, tb.y * inv1, tb.z * inv2, tb.w * inv3);
        s_ta[tid] = (tb.z - tb.x) * (tb.w - tb.y);
        s_cls[tid] = tids[b * TT + tid];
    }
    __syncthreads();

    // ---- Phase 1: cost matrix -> smem (col-major) + gmem, one pass (bit-identical) ----
    const int t  = tid & 63;
    const int qg = tid >> 6;
    const float4 tr = s_tr[t];
    const float4 tn = s_tn[t];
    const float  ta = s_ta[t];
    const int    cl = s_cls[t];

    const float* lg   = logits + (size_t)b * QQ * NCLS;
    float*       Cout = out    + (size_t)b * QQ * TT;

    #pragma unroll 4
    for (int k = 0; k < 32; k++) {
        int q = qg + (k << 4);
        if (q >= QQ) break;

        float4 pb = ((const float4*)pboxes)[b * QQ + q];   // uniform within warp
        float bnx = pb.x * inv0, bny = pb.y * inv1;
        float bnz = pb.z * inv2, bnw = pb.w * inv3;
        float pa  = (pb.z - pb.x) * (pb.w - pb.y);

        float x = __ldg(lg + q * NCLS + cl);
        float p = 1.0f / (1.0f + expf(-x));
        float omp = 1.0f - p;
        float pos = 0.25f * omp * omp * (-logf(p + 1e-8f));
        float neg = 0.75f * p * p * (-log1pf(-p + 1e-8f));
        float ccost = pos - neg;

        float l1 = fabsf(bnx - tn.x) + fabsf(bny - tn.y)
                 + fabsf(bnz - tn.z) + fabsf(bnw - tn.w);

        float iwd = fmaxf(fminf(pb.z, tr.z) - fmaxf(pb.x, tr.x), 0.0f);
        float ihd = fmaxf(fminf(pb.w, tr.w) - fmaxf(pb.y, tr.y), 0.0f);
        float inter = iwd * ihd;
        float uni = pa + ta - inter;
        float iou = inter / uni;
        float ewd = fmaxf(fmaxf(pb.z, tr.z) - fminf(pb.x, tr.x), 0.0f);
        float ehd = fmaxf(fmaxf(pb.w, tr.w) - fminf(pb.y, tr.y), 0.0f);
        float enc = ewd * ehd;
        float giou = iou - (enc - uni) / enc;

        float cost = 5.0f * l1 + 2.0f * ccost - 2.0f * giou;
        Cm[t * CSTR + q] = cost;     // conflict-free
        Cout[q * TT + t] = cost;     // coalesced
    }
    __syncthreads();

    // ---- Phase 2: initial exact top-2 per column; warp w -> cols w, w+32 ----
    {
        unsigned v1, r1, v2, r2;
        colscan2(Cm, wrp, lane, v1, r1, v2, r2);
        if (lane == 0) { s_v1[wrp] = v1; s_r1[wrp] = r1; s_v2[wrp] = v2; s_r2[wrp] = r2; }
        colscan2(Cm, wrp + 32, lane, v1, r1, v2, r2);
        if (lane == 0) {
            s_v1[wrp + 32] = v1; s_r1[wrp + 32] = r1;
            s_v2[wrp + 32] = v2; s_r2[wrp + 32] = r2;
        }
    }
    __syncthreads();

    if (wrp != 0) return;   // greedy: warp 0 only

    // ---- Phase 3: greedy with top-2 cursors (cur + backup per column) ----
    unsigned v0 = s_v1[lane],      r0 = s_r1[lane];        // col = lane      (current)
    unsigned w0 = s_v2[lane],      s0 = s_r2[lane];        //                 (backup)
    unsigned v1 = s_v1[lane + 32], r1 = s_r1[lane + 32];   // col = lane+32
    unsigned w1 = s_v2[lane + 32], s1 = s_r2[lane + 32];
    const float FINF = __int_as_float(0x7F800000);

    float* rows_out = out + (size_t)BB * QQ * TT + (size_t)b * TT;
    float* cols_out = rows_out + (size_t)BB * TT;

    #pragma unroll 1
    for (int st = 0; st < TT; st++) {
        unsigned m = __reduce_min_sync(FULL, v0 < v1 ? v0 : v1);
        unsigned cand = 0xFFFFFFFFu;
        if (v0 == m) cand = r0;
        if (v1 == m && r1 < cand) cand = r1;
        unsigned r = __reduce_min_sync(FULL, cand);   // exact (value, ravel) tie-break

        int i = (int)(r >> 6);
        int j = (int)(r & 63u);
        if (lane == 0) { rows_out[st] = (float)i; cols_out[st] = (float)j; }
        if (st == TT - 1) break;

        // kill column j
        if (lane == (j & 31)) { if (j < 32) v0 = DEADK; else v1 = DEADK; }

        // cursor maintenance (register-only, exact)
        bool need0 = false, need1 = false;
        if (v0 != DEADK) {
            if (w0 != DEADK && (s0 >> 6) == (unsigned)i) w0 = DEADK;   // backup row died
            if ((r0 >> 6) == (unsigned)i) {                            // cur row died
                if (w0 != DEADK) { v0 = w0; r0 = s0; w0 = DEADK; }     // exact promotion
                else need0 = true;
            }
        }
        if (v1 != DEADK) {
            if (w1 != DEADK && (s1 >> 6) == (unsigned)i) w1 = DEADK;
            if ((r1 >> 6) == (unsigned)i) {
                if (w1 != DEADK) { v1 = w1; r1 = s1; w1 = DEADK; }
                else need1 = true;
            }
        }

        // poison row i in every column (keeps rescans maskless)
        Cm[lane * CSTR + i] = FINF;
        Cm[(lane + 32) * CSTR + i] = FINF;

        // rare fallback: full colscan2 refills cur + backup
        unsigned bal0 = __ballot_sync(FULL, need0);
        unsigned bal1 = __ballot_sync(FULL, need1);
        if (bal0 | bal1) {
            __syncwarp();   // poisons visible before rescans
            while (bal0) {
                int c = __ffs(bal0) - 1; bal0 &= bal0 - 1;
                unsigned a, bri, d, e;
                colscan2(Cm, c, lane, a, bri, d, e);
                if (lane == c) { v0 = a; r0 = bri; w0 = d; s0 = e; }
            }
            while (bal1) {
                int c = __ffs(bal1) - 1; bal1 &= bal1 - 1;
                unsigned a, bri, d, e;
                colscan2(Cm, c + 32, lane, a, bri, d, e);
                if (lane == c) { v1 = a; r1 = bri; w1 = d; s1 = e; }
            }
        }
    }
}

extern "C" void kernel_launch(void* const* d_in, const int* in_sizes, int n_in,
                              void* d_out, int out_size) {
    const float* logits = (const float*)d_in[0];   // [128,500,80]
    const float* pboxes = (const float*)d_in[1];   // [128,500,4]
    const int*   tids   = (const int*)  d_in[2];   // [128,64]
    const float* tboxes = (const float*)d_in[3];   // [128,64,4]
    const float* imgsz  = (const float*)d_in[4];   // [128,4]
    float* out = (float*)d_out;

    cudaFuncSetAttribute(hungarian_fused,
                         cudaFuncAttributeMaxDynamicSharedMemorySize, SMEM_SZ);
    hungarian_fused<<<BB, NT, SMEM_SZ>>>(logits, pboxes, tids, tboxes, imgsz, out);
}